// round 5
// baseline (speedup 1.0000x reference)
#include <cuda_runtime.h>
#include <cuda_bf16.h>
#include <stdint.h>

// LengthRegulator: B=32, S=1024, E=256
//   cum = cumsum(duration, axis=1); mel_len = cum[:, -1]; max_mel = max(mel_len)
//   out[b, t, :] = x[b, idx(b,t), :]  where idx = searchsorted(cum[b], t, 'right')
//   tail rows (t >= mel_len[b]) zero; mask[b,t] = (t >= mel_len[b]) ? 1 : 0
// Output buffer: [ out (B*max_mel*E f32) | mask (B*max_mel f32) ] if has_mask.
//
// R3: expand processes 4 rows/warp (MLP 2 -> 8, latency-bound fix);
//     mask writes moved to scan kernel (coalesced instead of per-warp 4B).

#define BB 32
#define SS 1024
#define EE 256
#define MAXM_PAD 7168   // max possible mel length = 7 * 1024

#define WPB 8           // warps per block (expand)
#define RPW 4           // rows per warp (expand)

__device__ int g_idx[BB * MAXM_PAD];  // source row per output row
__device__ int g_mel[BB];             // mel_len per batch

// ---------------------------------------------------------------------------
// Kernel 1: per-batch inclusive scan + scatter inverse index + mask write.
// One block per batch, 1024 threads. Handles int64 or int32 duration
// (int64 LE => all odd 32-bit words are zero high-halves; dur values 0..7).
// ---------------------------------------------------------------------------
__global__ void lr_scan_kernel(const void* __restrict__ dur_raw,
                               float* __restrict__ mask,
                               int max_mel, int has_mask) {
    __shared__ int warp_sums[32];
    __shared__ int s_is64;
    __shared__ int s_L;

    const int b   = blockIdx.x;
    const int tid = threadIdx.x;

    if (tid == 0) {
        const unsigned* w = (const unsigned*)dur_raw;
        unsigned acc = 0;
        #pragma unroll
        for (int i = 1; i < 256; i += 2) acc |= w[i];  // 128 odd words
        s_is64 = (acc == 0u) ? 1 : 0;
    }
    __syncthreads();

    int v;
    if (s_is64) {
        v = (int)((const long long*)dur_raw)[b * SS + tid];
    } else {
        v = ((const int*)dur_raw)[b * SS + tid];
    }

    // warp inclusive scan
    const int lane = tid & 31;
    const int wid  = tid >> 5;
    int sv = v;
    #pragma unroll
    for (int o = 1; o < 32; o <<= 1) {
        int n = __shfl_up_sync(0xffffffffu, sv, o);
        if (lane >= o) sv += n;
    }
    if (lane == 31) warp_sums[wid] = sv;
    __syncthreads();

    if (wid == 0) {
        int ws = warp_sums[lane];
        #pragma unroll
        for (int o = 1; o < 32; o <<= 1) {
            int n = __shfl_up_sync(0xffffffffu, ws, o);
            if (lane >= o) ws += n;
        }
        warp_sums[lane] = ws;
    }
    __syncthreads();

    const int incl = sv + (wid > 0 ? warp_sums[wid - 1] : 0);
    const int excl = incl - v;

    // scatter: output rows [excl, incl) come from source row tid
    int* __restrict__ row = &g_idx[b * MAXM_PAD];
    for (int t = excl; t < incl; ++t) row[t] = tid;

    if (tid == SS - 1) { g_mel[b] = incl; s_L = incl; }
    __syncthreads();

    // coalesced mask write for this batch: mask[b,t] = (t >= L)
    if (has_mask) {
        const int L = s_L;
        float* __restrict__ mrow = mask + (size_t)b * max_mel;
        for (int t = tid; t < max_mel; t += SS)
            mrow[t] = (t >= L) ? 1.0f : 0.0f;
    }
}

// ---------------------------------------------------------------------------
// Kernel 2: expand. 4 rows per warp for MLP. grid = (ceil(max_mel/(WPB*RPW)), B).
// Per warp: 4 independent idx loads -> 8 independent LDG.128 -> 8 STG.128
// (streaming) covering 4KB of contiguous output. Tail rows zero-filled.
// ---------------------------------------------------------------------------
__global__ void lr_expand_kernel(const float* __restrict__ x,
                                 float* __restrict__ out,
                                 int max_mel) {
    const int b    = blockIdx.y;
    const int t0   = (blockIdx.x * WPB + (threadIdx.x >> 5)) * RPW;
    const int lane = threadIdx.x & 31;
    if (t0 >= max_mel) return;

    const int L = g_mel[b];
    const int* __restrict__ idxrow = &g_idx[b * MAXM_PAD];
    const float* __restrict__ xb = x + (size_t)b * SS * EE;

    // phase 1: gather source indices (independent uniform loads)
    int s[RPW];
    #pragma unroll
    for (int i = 0; i < RPW; ++i) {
        const int t = t0 + i;
        s[i] = (t < L) ? idxrow[t] : -1;      // t >= max_mel implies t >= L
    }

    // phase 2: 8 independent 16B loads
    float4 v[RPW][2];
    const float4 z = make_float4(0.f, 0.f, 0.f, 0.f);
    #pragma unroll
    for (int i = 0; i < RPW; ++i) {
        if (s[i] >= 0) {
            const float4* __restrict__ xr = (const float4*)(xb + (size_t)s[i] * EE);
            v[i][0] = __ldg(&xr[lane]);
            v[i][1] = __ldg(&xr[lane + 32]);
        } else {
            v[i][0] = z; v[i][1] = z;
        }
    }

    // phase 3: streaming stores, contiguous 4KB per warp
    float4* __restrict__ obase =
        (float4*)(out + ((size_t)b * max_mel + t0) * EE);
    #pragma unroll
    for (int i = 0; i < RPW; ++i) {
        if (t0 + i < max_mel) {
            __stcs(&obase[i * (EE / 4) + lane],      v[i][0]);
            __stcs(&obase[i * (EE / 4) + lane + 32], v[i][1]);
        }
    }
}

// ---------------------------------------------------------------------------
extern "C" void kernel_launch(void* const* d_in, const int* in_sizes, int n_in,
                              void* d_out, int out_size) {
    (void)in_sizes; (void)n_in;
    const float* x   = (const float*)d_in[0];
    const void*  dur = d_in[1];
    float* out = (float*)d_out;

    // Derive max_mel / layout from out_size (fixed per run).
    int has_mask, max_mel;
    if (out_size % (BB * (EE + 1)) == 0) {
        has_mask = 1;
        max_mel  = out_size / (BB * (EE + 1));
    } else {
        has_mask = 0;
        max_mel  = out_size / (BB * EE);
    }

    float* mask = out + (size_t)BB * max_mel * EE;
    lr_scan_kernel<<<BB, SS>>>(dur, mask, max_mel, has_mask);

    dim3 grid((max_mel + WPB * RPW - 1) / (WPB * RPW), BB);
    lr_expand_kernel<<<grid, WPB * 32>>>(x, out, max_mel);
}

// round 8
// speedup vs baseline: 1.1019x; 1.1019x over previous
#include <cuda_runtime.h>
#include <cuda_bf16.h>
#include <stdint.h>

// LengthRegulator: B=32, S=1024, E=256
//   cum = cumsum(duration, axis=1); mel_len = cum[:, -1]; max_mel = max(mel_len)
//   out[b, t, :] = x[b, idx(b,t), :]  where idx = searchsorted(cum[b], t, 'right')
//   tail rows (t >= mel_len[b]) zero; mask[b,t] = (t >= mel_len[b]) ? 1 : 0
// Output buffer: [ out (B*max_mel*E f32) | mask (B*max_mel f32) ] if has_mask.
//
// R5: SINGLE fused kernel. Each block (owning a 32-row output window of one
// batch) redundantly recomputes the batch cumsum from duration (8KB, L2-hot),
// scatters source indices intersecting its window into smem, then does the
// 4-rows-per-warp vectorized copy. Eliminates the scan kernel + launch gap
// (~4.9us of the 29.4us total).

#define BB 32
#define SS 1024
#define EE 256

#define WPB   8            // warps per block
#define RPW   4            // rows per warp
#define WIN   (WPB * RPW)  // 32 output rows per block
#define NTHR  256          // threads per block
#define EPT   4            // duration elements per thread (1024/256)

__global__ __launch_bounds__(NTHR)
void lr_fused_kernel(const float* __restrict__ x,
                     const void* __restrict__ dur_raw,
                     float* __restrict__ out,
                     int max_mel, int has_mask) {
    __shared__ int s_idx[WIN];     // source row for each window position
    __shared__ int s_warpsum[8];
    __shared__ int s_is64;

    const int b   = blockIdx.y;
    const int W0  = blockIdx.x * WIN;      // first output row of this block
    const int tid = threadIdx.x;
    const int lane = tid & 31;
    const int wid  = tid >> 5;

    // ---- dtype detect: int64 LE => odd 32-bit words are zero high-halves.
    // Warp 0 checks 128 odd words (dur values 0..7 => false-positive ~8^-128).
    if (wid == 0) {
        const unsigned* w = (const unsigned*)dur_raw;
        unsigned acc = 0;
        #pragma unroll
        for (int k = 0; k < 4; ++k) acc |= w[2 * (lane * 4 + k) + 1];
        unsigned any = __any_sync(0xffffffffu, acc != 0u);
        if (lane == 0) s_is64 = any ? 0 : 1;
    }
    __syncthreads();

    // ---- load 4 durations per thread for this batch
    int d[EPT];
    if (s_is64) {
        const long long* p = (const long long*)dur_raw + (size_t)b * SS + tid * EPT;
        #pragma unroll
        for (int e = 0; e < EPT; ++e) d[e] = (int)p[e];
    } else {
        const int* p = (const int*)dur_raw + (size_t)b * SS + tid * EPT;
        #pragma unroll
        for (int e = 0; e < EPT; ++e) d[e] = p[e];
    }

    // ---- block inclusive scan of 1024 durations (4/thread)
    int pfx[EPT];
    pfx[0] = d[0];
    #pragma unroll
    for (int e = 1; e < EPT; ++e) pfx[e] = pfx[e - 1] + d[e];
    const int tot = pfx[EPT - 1];

    int sv = tot;                                   // warp inclusive scan of totals
    #pragma unroll
    for (int o = 1; o < 32; o <<= 1) {
        int n = __shfl_up_sync(0xffffffffu, sv, o);
        if (lane >= o) sv += n;
    }
    if (lane == 31) s_warpsum[wid] = sv;
    __syncthreads();
    if (wid == 0) {
        int ws = (lane < 8) ? s_warpsum[lane] : 0;
        #pragma unroll
        for (int o = 1; o < 8; o <<= 1) {
            int n = __shfl_up_sync(0xffffffffu, ws, o);
            if (lane >= o) ws += n;
        }
        if (lane < 8) s_warpsum[lane] = ws;
    }
    __syncthreads();

    const int thr_base = (sv - tot) + (wid > 0 ? s_warpsum[wid - 1] : 0);
    const int L = s_warpsum[7];                     // mel_len[b]

    // ---- scatter: source element 4*tid+e covers output rows
    // [thr_base+pfx[e-1], thr_base+pfx[e]); intersect with [W0, W0+WIN)
    const int W1 = W0 + WIN;
    {
        int exc = thr_base;
        #pragma unroll
        for (int e = 0; e < EPT; ++e) {
            const int inc = thr_base + pfx[e];
            int lo = exc > W0 ? exc : W0;
            int hi = inc < W1 ? inc : W1;
            for (int t = lo; t < hi; ++t) s_idx[t - W0] = tid * EPT + e;
            exc = inc;
        }
    }
    __syncthreads();

    // ---- mask for this window (coalesced, one 128B store per block)
    if (has_mask && tid < WIN) {
        const int t = W0 + tid;
        if (t < max_mel)
            out[(size_t)BB * max_mel * EE + (size_t)b * max_mel + t] =
                (t >= L) ? 1.0f : 0.0f;
    }

    // ---- expand: 4 rows per warp, 8 independent 16B loads then 8 streaming stores
    const int t0 = W0 + (wid * RPW);
    const float* __restrict__ xb = x + (size_t)b * SS * EE;

    int s[RPW];
    #pragma unroll
    for (int i = 0; i < RPW; ++i) {
        const int t = t0 + i;
        s[i] = (t < L && t < max_mel) ? s_idx[t - W0] : -1;
    }

    float4 v[RPW][2];
    const float4 z = make_float4(0.f, 0.f, 0.f, 0.f);
    #pragma unroll
    for (int i = 0; i < RPW; ++i) {
        if (s[i] >= 0) {
            const float4* __restrict__ xr = (const float4*)(xb + (size_t)s[i] * EE);
            v[i][0] = __ldg(&xr[lane]);
            v[i][1] = __ldg(&xr[lane + 32]);
        } else {
            v[i][0] = z; v[i][1] = z;
        }
    }

    float4* __restrict__ obase =
        (float4*)(out + ((size_t)b * max_mel + t0) * EE);
    #pragma unroll
    for (int i = 0; i < RPW; ++i) {
        if (t0 + i < max_mel) {
            __stcs(&obase[i * (EE / 4) + lane],      v[i][0]);
            __stcs(&obase[i * (EE / 4) + lane + 32], v[i][1]);
        }
    }
}

// ---------------------------------------------------------------------------
extern "C" void kernel_launch(void* const* d_in, const int* in_sizes, int n_in,
                              void* d_out, int out_size) {
    (void)in_sizes; (void)n_in;
    const float* x   = (const float*)d_in[0];
    const void*  dur = d_in[1];
    float* out = (float*)d_out;

    // Derive max_mel / layout from out_size (fixed per run).
    int has_mask, max_mel;
    if (out_size % (BB * (EE + 1)) == 0) {
        has_mask = 1;
        max_mel  = out_size / (BB * (EE + 1));
    } else {
        has_mask = 0;
        max_mel  = out_size / (BB * EE);
    }

    dim3 grid((max_mel + WIN - 1) / WIN, BB);
    lr_fused_kernel<<<grid, NTHR>>>(x, dur, out, max_mel, has_mask);
}

// round 12
// speedup vs baseline: 1.1737x; 1.0651x over previous
#include <cuda_runtime.h>
#include <cuda_bf16.h>
#include <stdint.h>

// LengthRegulator: B=32, S=1024, E=256
//   cum = cumsum(duration, axis=1); mel_len = cum[:, -1]; max_mel = max(mel_len)
//   out[b, t, :] = x[b, idx(b,t), :]  where idx = searchsorted(cum[b], t, 'right')
//   tail rows (t >= mel_len[b]) zero; mask[b,t] = (t >= mel_len[b]) ? 1 : 0
// Output buffer: [ out (B*max_mel*E f32) | mask (B*max_mel f32) ] if has_mask.
//
// R8: fused kernel, window doubled to 64 rows/block (512 thr, 16 warps).
// Halves block count -> halves redundant per-block scan work (the part the
// R5 profile showed was not hidden), copy phase unchanged.

#define BB 32
#define SS 1024
#define EE 256

#define WPB   16           // warps per block
#define RPW   4            // rows per warp
#define WIN   (WPB * RPW)  // 64 output rows per block
#define NTHR  512          // threads per block
#define EPT   2            // duration elements per thread (1024/512)

__global__ __launch_bounds__(NTHR)
void lr_fused_kernel(const float* __restrict__ x,
                     const void* __restrict__ dur_raw,
                     float* __restrict__ out,
                     int max_mel, int has_mask) {
    __shared__ int s_idx[WIN];      // source row for each window position
    __shared__ int s_warpsum[WPB];
    __shared__ int s_is64;

    const int b    = blockIdx.y;
    const int W0   = blockIdx.x * WIN;     // first output row of this block
    const int tid  = threadIdx.x;
    const int lane = tid & 31;
    const int wid  = tid >> 5;

    // ---- dtype detect: int64 LE => odd 32-bit words are zero high-halves.
    // Warp 0 checks 128 odd words (dur in 0..7 => false-positive ~8^-128).
    if (wid == 0) {
        const unsigned* w = (const unsigned*)dur_raw;
        unsigned acc = 0;
        #pragma unroll
        for (int k = 0; k < 4; ++k) acc |= w[2 * (lane * 4 + k) + 1];
        unsigned any = __any_sync(0xffffffffu, acc != 0u);
        if (lane == 0) s_is64 = any ? 0 : 1;
    }
    __syncthreads();

    // ---- load 2 durations per thread for this batch
    int d[EPT];
    if (s_is64) {
        const long long* p = (const long long*)dur_raw + (size_t)b * SS + tid * EPT;
        #pragma unroll
        for (int e = 0; e < EPT; ++e) d[e] = (int)p[e];
    } else {
        const int* p = (const int*)dur_raw + (size_t)b * SS + tid * EPT;
        #pragma unroll
        for (int e = 0; e < EPT; ++e) d[e] = p[e];
    }

    // ---- block inclusive scan of 1024 durations (2/thread)
    int pfx[EPT];
    pfx[0] = d[0];
    #pragma unroll
    for (int e = 1; e < EPT; ++e) pfx[e] = pfx[e - 1] + d[e];
    const int tot = pfx[EPT - 1];

    int sv = tot;                                    // warp inclusive scan
    #pragma unroll
    for (int o = 1; o < 32; o <<= 1) {
        int n = __shfl_up_sync(0xffffffffu, sv, o);
        if (lane >= o) sv += n;
    }
    if (lane == 31) s_warpsum[wid] = sv;
    __syncthreads();
    if (wid == 0) {
        int ws = (lane < WPB) ? s_warpsum[lane] : 0;
        #pragma unroll
        for (int o = 1; o < WPB; o <<= 1) {
            int n = __shfl_up_sync(0xffffffffu, ws, o);
            if (lane >= o) ws += n;
        }
        if (lane < WPB) s_warpsum[lane] = ws;
    }
    __syncthreads();

    const int thr_base = (sv - tot) + (wid > 0 ? s_warpsum[wid - 1] : 0);
    const int L = s_warpsum[WPB - 1];                // mel_len[b]

    // ---- scatter: source element EPT*tid+e covers output rows
    // [thr_base+pfx[e-1], thr_base+pfx[e]); intersect with [W0, W0+WIN)
    const int W1 = W0 + WIN;
    {
        int exc = thr_base;
        #pragma unroll
        for (int e = 0; e < EPT; ++e) {
            const int inc = thr_base + pfx[e];
            int lo = exc > W0 ? exc : W0;
            int hi = inc < W1 ? inc : W1;
            for (int t = lo; t < hi; ++t) s_idx[t - W0] = tid * EPT + e;
            exc = inc;
        }
    }
    __syncthreads();

    // ---- mask for this window (coalesced)
    if (has_mask && tid < WIN) {
        const int t = W0 + tid;
        if (t < max_mel)
            out[(size_t)BB * max_mel * EE + (size_t)b * max_mel + t] =
                (t >= L) ? 1.0f : 0.0f;
    }

    // ---- expand: 4 rows/warp, 8 independent 16B loads -> 8 streaming stores
    const int t0 = W0 + wid * RPW;
    const float* __restrict__ xb = x + (size_t)b * SS * EE;

    int s[RPW];
    #pragma unroll
    for (int i = 0; i < RPW; ++i) {
        const int t = t0 + i;
        s[i] = (t < L && t < max_mel) ? s_idx[t - W0] : -1;
    }

    float4 v[RPW][2];
    const float4 z = make_float4(0.f, 0.f, 0.f, 0.f);
    #pragma unroll
    for (int i = 0; i < RPW; ++i) {
        if (s[i] >= 0) {
            const float4* __restrict__ xr = (const float4*)(xb + (size_t)s[i] * EE);
            v[i][0] = __ldg(&xr[lane]);
            v[i][1] = __ldg(&xr[lane + 32]);
        } else {
            v[i][0] = z; v[i][1] = z;
        }
    }

    float4* __restrict__ obase =
        (float4*)(out + ((size_t)b * max_mel + t0) * EE);
    #pragma unroll
    for (int i = 0; i < RPW; ++i) {
        if (t0 + i < max_mel) {
            __stcs(&obase[i * (EE / 4) + lane],      v[i][0]);
            __stcs(&obase[i * (EE / 4) + lane + 32], v[i][1]);
        }
    }
}

// ---------------------------------------------------------------------------
extern "C" void kernel_launch(void* const* d_in, const int* in_sizes, int n_in,
                              void* d_out, int out_size) {
    (void)in_sizes; (void)n_in;
    const float* x   = (const float*)d_in[0];
    const void*  dur = d_in[1];
    float* out = (float*)d_out;

    // Derive max_mel / layout from out_size (fixed per run).
    int has_mask, max_mel;
    if (out_size % (BB * (EE + 1)) == 0) {
        has_mask = 1;
        max_mel  = out_size / (BB * (EE + 1));
    } else {
        has_mask = 0;
        max_mel  = out_size / (BB * EE);
    }

    dim3 grid((max_mel + WIN - 1) / WIN, BB);
    lr_fused_kernel<<<grid, NTHR>>>(x, dur, out, max_mel, has_mask);
}